// round 10
// baseline (speedup 1.0000x reference)
#include <cuda_runtime.h>
#include <math.h>
#include <stdint.h>

// ---------------------------------------------------------------------------
// Problem constants
// ---------------------------------------------------------------------------
#define Bz 4
#define Tz 2048
#define Cz 1024
#define Hz 16
#define DKz 64
#define Mz (Bz * Tz)
#define N3z (3 * Cz)

#define LOG2E 1.4426950408889634f

// Scratch
__device__ float g_qkv[3 * Bz * Hz * Tz * DKz];   // [3][B][H][T][DK]
__device__ float g_att[(size_t)Mz * Cz];          // [B*T][C]

// ---------------------------------------------------------------------------
// Helpers
// ---------------------------------------------------------------------------
__device__ __forceinline__ uint32_t f2tf32(float x) {
    uint32_t u;
    asm("cvt.rna.tf32.f32 %0, %1;" : "=r"(u) : "f"(x));
    return u;
}

__device__ __forceinline__ void mma_tf32(float c[4], uint4 a, uint2 b) {
    asm volatile(
        "mma.sync.aligned.m16n8k8.row.col.f32.tf32.tf32.f32 "
        "{%0,%1,%2,%3}, {%4,%5,%6,%7}, {%8,%9}, {%0,%1,%2,%3};"
        : "+f"(c[0]), "+f"(c[1]), "+f"(c[2]), "+f"(c[3])
        : "r"(a.x), "r"(a.y), "r"(a.z), "r"(a.w), "r"(b.x), "r"(b.y));
}

// FFMA-only exp2 (input <= 0; clamped). Avoids the MUFU pipe floor.
__device__ __forceinline__ float fexp2(float x) {
    x = fmaxf(x, -126.f);
    float fl = floorf(x);
    float f  = x - fl;
    float p  = 1.5403530393381608e-4f;
    p = fmaf(p, f, 1.3333558146428443e-3f);
    p = fmaf(p, f, 9.6181291076284770e-3f);
    p = fmaf(p, f, 5.5504108664821580e-2f);
    p = fmaf(p, f, 2.4022650695910070e-1f);
    p = fmaf(p, f, 6.9314718055994530e-1f);
    p = fmaf(p, f, 1.0f);
    int e = (int)fl;
    return __uint_as_float(__float_as_uint(p) + ((uint32_t)e << 23));
}

// ---------------------------------------------------------------------------
// TF32 GEMM, double-buffered, register-prefetch for BOTH operands into
// fragment-major swizzled smem (zero cvt / minimal LDS in the compute loop).
//   C[m,n] = sum_k Asrc[m,k] * W[n,k]
// BM=BN=128, BK=32; 256 threads = 8 warps, warp tile 64(m) x 32(n).
// A frag read = 1x LDS.128; B frag read = 1x LDS.64.
// Dynamic smem: 2*4096 (A) + 2*4096 (B) u32 = 65536 B -> 2 CTAs/SM.
// ---------------------------------------------------------------------------
#define GEMM_SMEM_BYTES ((2 * 4096 + 2 * 4096) * 4)

template <bool SCATTER>
__global__ __launch_bounds__(256, 2) void gemm_tf32(const float* __restrict__ A_arg,
                                                    const float* __restrict__ W,
                                                    float* __restrict__ out) {
    extern __shared__ uint32_t dsm[];
    uint32_t* sA = dsm;               // 2 x 4096
    uint32_t* sB = dsm + 2 * 4096;    // 2 x 4096 (fragment-major tf32)

    const float* __restrict__ A = SCATTER ? A_arg : (const float*)g_att;

    const int tid  = threadIdx.x;
    const int lane = tid & 31;
    const int wid  = tid >> 5;
    const int wm   = wid & 1;
    const int wn   = wid >> 1;
    const int bm   = blockIdx.y * 128;
    const int bn   = blockIdx.x * 128;
    const int g    = lane >> 2;
    const int tig  = lane & 3;

    // per-thread load coords (4 chunks of 16B for each of A and B)
    const int row_ld = tid >> 3;            // 0..31 (+32 per chunk)
    const int kc_ld  = (tid & 7) << 2;      // 0,4,...,28
    const int k8_ld  = kc_ld >> 3;
    const int chi_ld = (kc_ld >> 2) & 1;
    const int swz_ld = (k8_ld << 2) ^ k8_ld;

    float c[4][4][4];
#pragma unroll
    for (int i = 0; i < 4; i++)
#pragma unroll
        for (int j = 0; j < 4; j++)
#pragma unroll
            for (int r = 0; r < 4; r++) c[i][j][r] = 0.f;

    float4 pa[4], pb[4];   // prefetch registers

    auto issueAB = [&](int k0) {
#pragma unroll
        for (int l = 0; l < 4; l++) {
            pa[l] = *(const float4*)(A + (size_t)(bm + row_ld + l * 32) * Cz + k0 + kc_ld);
            pb[l] = *(const float4*)(W + (size_t)(bn + row_ld + l * 32) * Cz + k0 + kc_ld);
        }
    };
    auto storeAB = [&](int buf) {
        uint32_t* sAb = sA + buf * 4096;
        uint32_t* sBb = sB + buf * 4096;
#pragma unroll
        for (int l = 0; l < 4; l++) {
            const int row = row_ld + l * 32;
            // A: fragment layout (k8, m16) x 32 lanes x 4 regs
            {
                const int m16 = row >> 4;
                const int r   = row & 15;
                const int gg  = r & 7;
                const int reg = (r >> 3) + 2 * chi_ld;
                uint32_t* base = sAb + (size_t)(k8_ld * 8 + m16) * 128;
                base[(((gg << 2) + 0) ^ swz_ld) * 4 + reg] = f2tf32(pa[l].x);
                base[(((gg << 2) + 1) ^ swz_ld) * 4 + reg] = f2tf32(pa[l].y);
                base[(((gg << 2) + 2) ^ swz_ld) * 4 + reg] = f2tf32(pa[l].z);
                base[(((gg << 2) + 3) ^ swz_ld) * 4 + reg] = f2tf32(pa[l].w);
            }
            // B: fragment layout (k8, n8) x 32 lanes x 2 regs
            {
                const int n8 = row >> 3;
                const int gg = row & 7;
                uint32_t* base = sBb + (size_t)(k8_ld * 16 + n8) * 64;
                base[(((gg << 2) + 0) ^ swz_ld) * 2 + chi_ld] = f2tf32(pb[l].x);
                base[(((gg << 2) + 1) ^ swz_ld) * 2 + chi_ld] = f2tf32(pb[l].y);
                base[(((gg << 2) + 2) ^ swz_ld) * 2 + chi_ld] = f2tf32(pb[l].z);
                base[(((gg << 2) + 3) ^ swz_ld) * 2 + chi_ld] = f2tf32(pb[l].w);
            }
        }
    };

    // ---- prologue: tile 0 ----
    issueAB(0);
    storeAB(0);
    __syncthreads();

    const int KT = Cz / 32;
    for (int k = 0; k < KT; k++) {
        const int p = k & 1;
        if (k + 1 < KT) issueAB((k + 1) * 32);   // LDGs in flight during compute

        const uint32_t* sAb = sA + p * 4096;
        const uint32_t* sBb = sB + p * 4096;
#pragma unroll
        for (int k8 = 0; k8 < 4; k8++) {
            const int swz = (k8 << 2) ^ k8;
            const int lp  = lane ^ swz;
            uint4 af[4];
            uint2 bf[4];
#pragma unroll
            for (int i = 0; i < 4; i++)
                af[i] = *(const uint4*)(sAb + (size_t)(k8 * 8 + wm * 4 + i) * 128 + lp * 4);
#pragma unroll
            for (int j = 0; j < 4; j++)
                bf[j] = *(const uint2*)(sBb + (size_t)(k8 * 16 + wn * 4 + j) * 64 + lp * 2);
#pragma unroll
            for (int i = 0; i < 4; i++)
#pragma unroll
                for (int j = 0; j < 4; j++)
                    mma_tf32(c[i][j], af[i], bf[j]);
        }

        if (k + 1 < KT) {
            storeAB(p ^ 1);
            __syncthreads();
        }
    }

    // ---- epilogue ----
#pragma unroll
    for (int i = 0; i < 4; i++) {
        const int row0 = bm + wm * 64 + i * 16 + g;
#pragma unroll
        for (int j = 0; j < 4; j++) {
            const int col = bn + wn * 32 + j * 8 + tig * 2;
            if (SCATTER) {
                const int which = col >> 10;
                const int h     = (col >> 6) & (Hz - 1);
                const int d     = col & (DKz - 1);
#pragma unroll
                for (int hi = 0; hi < 2; hi++) {
                    const int m  = row0 + hi * 8;
                    const int bb = m >> 11;
                    const int t  = m & (Tz - 1);
                    float* dst = g_qkv +
                        ((size_t)((which * Bz + bb) * Hz + h) * Tz + t) * DKz + d;
                    *(float2*)dst = make_float2(c[i][j][hi * 2], c[i][j][hi * 2 + 1]);
                }
            } else {
#pragma unroll
                for (int hi = 0; hi < 2; hi++) {
                    const int m = row0 + hi * 8;
                    *(float2*)(out + (size_t)m * Cz + col) =
                        make_float2(c[i][j][hi * 2], c[i][j][hi * 2 + 1]);
                }
            }
        }
    }
}

// ---------------------------------------------------------------------------
// Kernel 2: causal flash attention with ALiBi — TF32 tensor cores.
// 128-thread CTAs (4 warps = 64 q rows) -> 2 CTAs/SM: decoupled barriers,
// one CTA's softmax overlaps the other's MMA. Key tiles of 64, double-buffered
// via register prefetch. Mask only on the diagonal tile (kt == qblk).
// ---------------------------------------------------------------------------
#define SK_STRIDE 68
#define SV_STRIDE 72
#define SK_WORDS (64 * SK_STRIDE)
#define SV_WORDS (64 * SV_STRIDE)
#define ATTN_SMEM_BYTES ((2 * SK_WORDS + 2 * SV_WORDS) * 4)

__global__ __launch_bounds__(128, 2) void attn_tc(const float* __restrict__ alibi) {
    extern __shared__ uint32_t asm_[];
    uint32_t* sK = asm_;                 // 2 x SK_WORDS
    uint32_t* sV = asm_ + 2 * SK_WORDS;  // 2 x SV_WORDS

    const int tid  = threadIdx.x;
    const int lane = tid & 31;
    const int w    = tid >> 5;           // 0..3
    const int g    = lane >> 2;
    const int tig  = lane & 3;
    const int qblk = (Tz / 64 - 1) - blockIdx.x;   // reverse: long blocks first
    const int h    = blockIdx.y;
    const int b    = blockIdx.z;
    const int q0   = qblk * 64;

    const float slope = alibi[(size_t)h * Tz * Tz + 1];
    const float sl2   = slope * LOG2E;
    const float sc2   = 0.125f * LOG2E;

    const float* Qg = g_qkv + ((size_t)((0 * Bz + b) * Hz + h) * Tz) * DKz;
    const float* Kg = g_qkv + ((size_t)((1 * Bz + b) * Hz + h) * Tz) * DKz;
    const float* Vg = g_qkv + ((size_t)((2 * Bz + b) * Hz + h) * Tz) * DKz;

    const int row0g = q0 + w * 16 + g;
    const int row1g = row0g + 8;

    // per-thread K/V load coords: 8 chunks of float4 per matrix
    const int r_ld  = tid >> 4;          // 0..7 (+8 per chunk)
    const int c4_ld = (tid & 15) << 2;   // 0..60

    float4 pk[8], pv[8];
    auto issueKV = [&](int kt) {
#pragma unroll
        for (int it = 0; it < 8; it++) {
            const int r = r_ld + it * 8;
            pk[it] = *(const float4*)(Kg + (size_t)(kt * 64 + r) * DKz + c4_ld);
            pv[it] = *(const float4*)(Vg + (size_t)(kt * 64 + r) * DKz + c4_ld);
        }
    };
    auto storeKV = [&](int buf) {
        uint32_t* sKb = sK + buf * SK_WORDS;
        uint32_t* sVb = sV + buf * SV_WORDS;
#pragma unroll
        for (int it = 0; it < 8; it++) {
            const int r = r_ld + it * 8;
            *(uint4*)&sKb[r * SK_STRIDE + c4_ld] =
                make_uint4(f2tf32(pk[it].x), f2tf32(pk[it].y),
                           f2tf32(pk[it].z), f2tf32(pk[it].w));
            *(uint4*)&sVb[r * SV_STRIDE + c4_ld] =
                make_uint4(f2tf32(pv[it].x), f2tf32(pv[it].y),
                           f2tf32(pv[it].z), f2tf32(pv[it].w));
        }
    };

    // Q fragments (registers)
    uint4 qf[8];
    {
        const float* q0p = Qg + (size_t)row0g * DKz;
        const float* q1p = Qg + (size_t)row1g * DKz;
#pragma unroll
        for (int s = 0; s < 8; s++) {
            qf[s].x = f2tf32(q0p[s * 8 + tig]);
            qf[s].y = f2tf32(q1p[s * 8 + tig]);
            qf[s].z = f2tf32(q0p[s * 8 + tig + 4]);
            qf[s].w = f2tf32(q1p[s * 8 + tig + 4]);
        }
    }

    float acc[8][4];
#pragma unroll
    for (int jd = 0; jd < 8; jd++)
#pragma unroll
        for (int r = 0; r < 4; r++) acc[jd][r] = 0.f;
    float m0 = -1e30f, m1 = -1e30f, l0 = 0.f, l1 = 0.f;

    const int  srcA = (lane & 0x1C) | (tig >> 1);
    const int  srcB = srcA + 2;
    const bool sel  = (tig & 1) != 0;

    // prologue: tile 0
    issueKV(0);
    storeKV(0);
    __syncthreads();

    for (int kt = 0; kt <= qblk; kt++) {
        const int  p      = kt & 1;
        const bool domask = (kt == qblk);

        if (kt < qblk) issueKV(kt + 1);   // overlap with compute below

        const uint32_t* sKb = sK + p * SK_WORDS;
        const uint32_t* sVb = sV + p * SV_WORDS;

        // ---- S = Q K^T ----
        float sc[8][4];
#pragma unroll
        for (int j = 0; j < 8; j++)
#pragma unroll
            for (int r = 0; r < 4; r++) sc[j][r] = 0.f;
#pragma unroll
        for (int s = 0; s < 8; s++) {
#pragma unroll
            for (int j = 0; j < 8; j++) {
                uint2 bk;
                bk.x = sKb[(j * 8 + g) * SK_STRIDE + s * 8 + tig];
                bk.y = sKb[(j * 8 + g) * SK_STRIDE + s * 8 + tig + 4];
                mma_tf32(sc[j], qf[s], bk);
            }
        }

        // ---- scale + alibi + causal, online softmax (log2 domain) ----
        const int key0 = kt * 64;
        float tmax0 = -1e30f, tmax1 = -1e30f;
#pragma unroll
        for (int j = 0; j < 8; j++) {
            const int ke = key0 + j * 8 + 2 * tig;
            float s00 = fmaf(sc[j][0], sc2, sl2 * (float)(ke - row0g));
            float s01 = fmaf(sc[j][1], sc2, sl2 * (float)(ke + 1 - row0g));
            float s10 = fmaf(sc[j][2], sc2, sl2 * (float)(ke - row1g));
            float s11 = fmaf(sc[j][3], sc2, sl2 * (float)(ke + 1 - row1g));
            if (domask) {
                if (ke     > row0g) s00 = -1e30f;
                if (ke + 1 > row0g) s01 = -1e30f;
                if (ke     > row1g) s10 = -1e30f;
                if (ke + 1 > row1g) s11 = -1e30f;
            }
            sc[j][0] = s00; sc[j][1] = s01; sc[j][2] = s10; sc[j][3] = s11;
            tmax0 = fmaxf(tmax0, fmaxf(s00, s01));
            tmax1 = fmaxf(tmax1, fmaxf(s10, s11));
        }
        tmax0 = fmaxf(tmax0, __shfl_xor_sync(0xffffffffu, tmax0, 1));
        tmax0 = fmaxf(tmax0, __shfl_xor_sync(0xffffffffu, tmax0, 2));
        tmax1 = fmaxf(tmax1, __shfl_xor_sync(0xffffffffu, tmax1, 1));
        tmax1 = fmaxf(tmax1, __shfl_xor_sync(0xffffffffu, tmax1, 2));

        const float mn0 = fmaxf(m0, tmax0);
        const float mn1 = fmaxf(m1, tmax1);
        const float corr0 = fexp2(m0 - mn0);
        const float corr1 = fexp2(m1 - mn1);
        m0 = mn0; m1 = mn1;

        uint4 pu[8];
        float rs0 = 0.f, rs1 = 0.f;
#pragma unroll
        for (int j = 0; j < 8; j++) {
            float p00 = fexp2(sc[j][0] - mn0);
            float p01 = fexp2(sc[j][1] - mn0);
            float p10 = fexp2(sc[j][2] - mn1);
            float p11 = fexp2(sc[j][3] - mn1);
            rs0 += p00 + p01;
            rs1 += p10 + p11;
            pu[j] = make_uint4(f2tf32(p00), f2tf32(p01), f2tf32(p10), f2tf32(p11));
        }
        rs0 += __shfl_xor_sync(0xffffffffu, rs0, 1);
        rs0 += __shfl_xor_sync(0xffffffffu, rs0, 2);
        rs1 += __shfl_xor_sync(0xffffffffu, rs1, 1);
        rs1 += __shfl_xor_sync(0xffffffffu, rs1, 2);
        l0 = l0 * corr0 + rs0;
        l1 = l1 * corr1 + rs1;
#pragma unroll
        for (int jd = 0; jd < 8; jd++) {
            acc[jd][0] *= corr0; acc[jd][1] *= corr0;
            acc[jd][2] *= corr1; acc[jd][3] *= corr1;
        }

        // ---- att += P @ V ----
#pragma unroll
        for (int s = 0; s < 8; s++) {
            uint32_t x00 = __shfl_sync(0xffffffffu, pu[s].x, srcA);
            uint32_t x01 = __shfl_sync(0xffffffffu, pu[s].y, srcA);
            uint32_t x10 = __shfl_sync(0xffffffffu, pu[s].z, srcA);
            uint32_t x11 = __shfl_sync(0xffffffffu, pu[s].w, srcA);
            uint32_t y00 = __shfl_sync(0xffffffffu, pu[s].x, srcB);
            uint32_t y01 = __shfl_sync(0xffffffffu, pu[s].y, srcB);
            uint32_t y10 = __shfl_sync(0xffffffffu, pu[s].z, srcB);
            uint32_t y11 = __shfl_sync(0xffffffffu, pu[s].w, srcB);
            uint4 aP;
            aP.x = sel ? x01 : x00;
            aP.y = sel ? x11 : x10;
            aP.z = sel ? y01 : y00;
            aP.w = sel ? y11 : y10;
#pragma unroll
            for (int jd = 0; jd < 8; jd++) {
                uint2 bv;
                bv.x = sVb[(s * 8 + tig)     * SV_STRIDE + jd * 8 + g];
                bv.y = sVb[(s * 8 + tig + 4) * SV_STRIDE + jd * 8 + g];
                mma_tf32(acc[jd], aP, bv);
            }
        }

        if (kt < qblk) {
            storeKV(p ^ 1);
            __syncthreads();
        }
    }

    // ---- normalize and write ----
    const float inv0 = 1.f / l0;
    const float inv1 = 1.f / l1;
    float* o0 = g_att + (size_t)(b * Tz + row0g) * Cz + h * DKz;
    float* o1 = g_att + (size_t)(b * Tz + row1g) * Cz + h * DKz;
#pragma unroll
    for (int jd = 0; jd < 8; jd++) {
        *(float2*)(o0 + jd * 8 + 2 * tig) =
            make_float2(acc[jd][0] * inv0, acc[jd][1] * inv0);
        *(float2*)(o1 + jd * 8 + 2 * tig) =
            make_float2(acc[jd][2] * inv1, acc[jd][3] * inv1);
    }
}

// ---------------------------------------------------------------------------
// Launch
// ---------------------------------------------------------------------------
extern "C" void kernel_launch(void* const* d_in, const int* in_sizes, int n_in,
                              void* d_out, int out_size) {
    const float* x     = (const float*)d_in[0];
    const float* alibi = (const float*)d_in[1];
    const float* Wqkv  = (const float*)d_in[2];
    const float* Wo    = (const float*)d_in[3];
    float* out = (float*)d_out;
    (void)in_sizes; (void)n_in; (void)out_size;

    cudaFuncSetAttribute(gemm_tf32<true>,
                         cudaFuncAttributeMaxDynamicSharedMemorySize, GEMM_SMEM_BYTES);
    cudaFuncSetAttribute(gemm_tf32<false>,
                         cudaFuncAttributeMaxDynamicSharedMemorySize, GEMM_SMEM_BYTES);
    cudaFuncSetAttribute(attn_tc,
                         cudaFuncAttributeMaxDynamicSharedMemorySize, ATTN_SMEM_BYTES);

    // 1. QKV projection (pipelined TF32), scatters to g_qkv
    gemm_tf32<true><<<dim3(N3z / 128, Mz / 128), 256, GEMM_SMEM_BYTES>>>(x, Wqkv, nullptr);

    // 2. Flash attention with ALiBi (TF32 + FFMA exp), 4-warp CTAs, 2/SM
    attn_tc<<<dim3(Tz / 64, Hz, Bz), 128, ATTN_SMEM_BYTES>>>(alibi);

    // 3. Output projection (pipelined TF32), A = g_att selected in device code
    gemm_tf32<false><<<dim3(Cz / 128, Mz / 128), 256, GEMM_SMEM_BYTES>>>(nullptr, Wo, out);
}

// round 11
// speedup vs baseline: 1.0325x; 1.0325x over previous
#include <cuda_runtime.h>
#include <math.h>
#include <stdint.h>

// ---------------------------------------------------------------------------
// Problem constants
// ---------------------------------------------------------------------------
#define Bz 4
#define Tz 2048
#define Cz 1024
#define Hz 16
#define DKz 64
#define Mz (Bz * Tz)
#define N3z (3 * Cz)

#define LOG2E 1.4426950408889634f

// Scratch
__device__ float g_qkv[3 * Bz * Hz * Tz * DKz];   // [3][B][H][T][DK]
__device__ float g_att[(size_t)Mz * Cz];          // [B*T][C]

// ---------------------------------------------------------------------------
// Helpers
// ---------------------------------------------------------------------------
__device__ __forceinline__ uint32_t f2tf32(float x) {
    uint32_t u;
    asm("cvt.rna.tf32.f32 %0, %1;" : "=r"(u) : "f"(x));
    return u;
}

__device__ __forceinline__ void mma_tf32(float c[4], uint4 a, uint2 b) {
    asm volatile(
        "mma.sync.aligned.m16n8k8.row.col.f32.tf32.tf32.f32 "
        "{%0,%1,%2,%3}, {%4,%5,%6,%7}, {%8,%9}, {%0,%1,%2,%3};"
        : "+f"(c[0]), "+f"(c[1]), "+f"(c[2]), "+f"(c[3])
        : "r"(a.x), "r"(a.y), "r"(a.z), "r"(a.w), "r"(b.x), "r"(b.y));
}

// FFMA-only exp2 (input <= 0; clamped). Avoids the MUFU pipe floor.
__device__ __forceinline__ float fexp2(float x) {
    x = fmaxf(x, -126.f);
    float fl = floorf(x);
    float f  = x - fl;
    float p  = 1.5403530393381608e-4f;
    p = fmaf(p, f, 1.3333558146428443e-3f);
    p = fmaf(p, f, 9.6181291076284770e-3f);
    p = fmaf(p, f, 5.5504108664821580e-2f);
    p = fmaf(p, f, 2.4022650695910070e-1f);
    p = fmaf(p, f, 6.9314718055994530e-1f);
    p = fmaf(p, f, 1.0f);
    int e = (int)fl;
    return __uint_as_float(__float_as_uint(p) + ((uint32_t)e << 23));
}

// ---------------------------------------------------------------------------
// TF32 GEMM: C[m,n] = sum_k Asrc[m,k] * W[n,k]
// BM=128, BN=256, BK=32; 256 threads = 8 warps; warp tile 64(m) x 64(n).
// Double-buffered, register prefetch for both operands, fragment-major
// swizzled smem (A frag = 1 LDS.128, B frag = 1 LDS.64, zero cvt in loop).
// smem: 2*4096 (A) + 2*8192 (B) u32 = 98304 B -> 1 CTA/SM.
// ---------------------------------------------------------------------------
#define GEMM_SMEM_BYTES ((2 * 4096 + 2 * 8192) * 4)

template <bool SCATTER>
__global__ __launch_bounds__(256, 1) void gemm_tf32(const float* __restrict__ A_arg,
                                                    const float* __restrict__ W,
                                                    float* __restrict__ out) {
    extern __shared__ uint32_t dsm[];
    uint32_t* sA = dsm;               // 2 x 4096
    uint32_t* sB = dsm + 2 * 4096;    // 2 x 8192

    const float* __restrict__ A = SCATTER ? A_arg : (const float*)g_att;

    const int tid  = threadIdx.x;
    const int lane = tid & 31;
    const int wid  = tid >> 5;
    const int wm   = wid & 1;    // 2 m-warps x 64 rows
    const int wn   = wid >> 1;   // 4 n-warps x 64 cols
    const int bm   = blockIdx.y * 128;
    const int bn   = blockIdx.x * 256;
    const int g    = lane >> 2;
    const int tig  = lane & 3;

    // load coords: A 4 chunks (rows 0..127 step 32), B 8 chunks (rows 0..255)
    const int row_ld = tid >> 3;            // 0..31
    const int kc_ld  = (tid & 7) << 2;      // 0,4,...,28
    const int k8_ld  = kc_ld >> 3;
    const int chi_ld = (kc_ld >> 2) & 1;
    const int swz_ld = (k8_ld << 2) ^ k8_ld;

    float c[4][8][4];
#pragma unroll
    for (int i = 0; i < 4; i++)
#pragma unroll
        for (int j = 0; j < 8; j++)
#pragma unroll
            for (int r = 0; r < 4; r++) c[i][j][r] = 0.f;

    float4 pa[4], pb[8];

    auto issueAB = [&](int k0) {
#pragma unroll
        for (int l = 0; l < 4; l++)
            pa[l] = *(const float4*)(A + (size_t)(bm + row_ld + l * 32) * Cz + k0 + kc_ld);
#pragma unroll
        for (int l = 0; l < 8; l++)
            pb[l] = *(const float4*)(W + (size_t)(bn + row_ld + l * 32) * Cz + k0 + kc_ld);
    };
    auto storeAB = [&](int buf) {
        uint32_t* sAb = sA + buf * 4096;
        uint32_t* sBb = sB + buf * 8192;
#pragma unroll
        for (int l = 0; l < 4; l++) {
            const int row = row_ld + l * 32;
            const int m16 = row >> 4;
            const int r   = row & 15;
            const int gg  = r & 7;
            const int reg = (r >> 3) + 2 * chi_ld;
            uint32_t* base = sAb + (size_t)(k8_ld * 8 + m16) * 128;
            base[(((gg << 2) + 0) ^ swz_ld) * 4 + reg] = f2tf32(pa[l].x);
            base[(((gg << 2) + 1) ^ swz_ld) * 4 + reg] = f2tf32(pa[l].y);
            base[(((gg << 2) + 2) ^ swz_ld) * 4 + reg] = f2tf32(pa[l].z);
            base[(((gg << 2) + 3) ^ swz_ld) * 4 + reg] = f2tf32(pa[l].w);
        }
#pragma unroll
        for (int l = 0; l < 8; l++) {
            const int row = row_ld + l * 32;
            const int n8  = row >> 3;
            const int gg  = row & 7;
            uint32_t* base = sBb + (size_t)(k8_ld * 32 + n8) * 64;
            base[(((gg << 2) + 0) ^ swz_ld) * 2 + chi_ld] = f2tf32(pb[l].x);
            base[(((gg << 2) + 1) ^ swz_ld) * 2 + chi_ld] = f2tf32(pb[l].y);
            base[(((gg << 2) + 2) ^ swz_ld) * 2 + chi_ld] = f2tf32(pb[l].z);
            base[(((gg << 2) + 3) ^ swz_ld) * 2 + chi_ld] = f2tf32(pb[l].w);
        }
    };

    // ---- prologue: tile 0 ----
    issueAB(0);
    storeAB(0);
    __syncthreads();

    const int KT = Cz / 32;
    for (int k = 0; k < KT; k++) {
        const int p = k & 1;
        if (k + 1 < KT) issueAB((k + 1) * 32);   // LDGs in flight during compute

        const uint32_t* sAb = sA + p * 4096;
        const uint32_t* sBb = sB + p * 8192;
#pragma unroll
        for (int k8 = 0; k8 < 4; k8++) {
            const int swz = (k8 << 2) ^ k8;
            const int lp  = lane ^ swz;
            uint4 af[4];
            uint2 bf[8];
#pragma unroll
            for (int i = 0; i < 4; i++)
                af[i] = *(const uint4*)(sAb + (size_t)(k8 * 8 + wm * 4 + i) * 128 + lp * 4);
#pragma unroll
            for (int j = 0; j < 8; j++)
                bf[j] = *(const uint2*)(sBb + (size_t)(k8 * 32 + wn * 8 + j) * 64 + lp * 2);
#pragma unroll
            for (int i = 0; i < 4; i++)
#pragma unroll
                for (int j = 0; j < 8; j++)
                    mma_tf32(c[i][j], af[i], bf[j]);
        }

        if (k + 1 < KT) {
            storeAB(p ^ 1);
            __syncthreads();
        }
    }

    // ---- epilogue ----
#pragma unroll
    for (int i = 0; i < 4; i++) {
        const int row0 = bm + wm * 64 + i * 16 + g;
#pragma unroll
        for (int j = 0; j < 8; j++) {
            const int col = bn + wn * 64 + j * 8 + tig * 2;
            if (SCATTER) {
                const int which = col >> 10;
                const int h     = (col >> 6) & (Hz - 1);
                const int d     = col & (DKz - 1);
#pragma unroll
                for (int hi = 0; hi < 2; hi++) {
                    const int m  = row0 + hi * 8;
                    const int bb = m >> 11;
                    const int t  = m & (Tz - 1);
                    float* dst = g_qkv +
                        ((size_t)((which * Bz + bb) * Hz + h) * Tz + t) * DKz + d;
                    *(float2*)dst = make_float2(c[i][j][hi * 2], c[i][j][hi * 2 + 1]);
                }
            } else {
#pragma unroll
                for (int hi = 0; hi < 2; hi++) {
                    const int m = row0 + hi * 8;
                    *(float2*)(out + (size_t)m * Cz + col) =
                        make_float2(c[i][j][hi * 2], c[i][j][hi * 2 + 1]);
                }
            }
        }
    }
}

// ---------------------------------------------------------------------------
// Kernel 2: causal flash attention with ALiBi — TF32 tensor cores (R9-best).
// 256 threads = 8 warps = 128 q rows; key tiles of 64, double-buffered via
// register prefetch. FFMA-only exp.
// ---------------------------------------------------------------------------
#define SK_STRIDE 68
#define SV_STRIDE 72
#define SK_WORDS (64 * SK_STRIDE)
#define SV_WORDS (64 * SV_STRIDE)
#define ATTN_SMEM_BYTES ((2 * SK_WORDS + 2 * SV_WORDS) * 4)

__global__ __launch_bounds__(256, 1) void attn_tc(const float* __restrict__ alibi) {
    extern __shared__ uint32_t asm_[];
    uint32_t* sK = asm_;                 // 2 x SK_WORDS
    uint32_t* sV = asm_ + 2 * SK_WORDS;  // 2 x SV_WORDS

    const int tid  = threadIdx.x;
    const int lane = tid & 31;
    const int w    = tid >> 5;
    const int g    = lane >> 2;
    const int tig  = lane & 3;
    const int qblk = (Tz / 128 - 1) - blockIdx.x;
    const int h    = blockIdx.y;
    const int b    = blockIdx.z;
    const int q0   = qblk * 128;

    const float slope = alibi[(size_t)h * Tz * Tz + 1];
    const float sl2   = slope * LOG2E;
    const float sc2   = 0.125f * LOG2E;

    const float* Qg = g_qkv + ((size_t)((0 * Bz + b) * Hz + h) * Tz) * DKz;
    const float* Kg = g_qkv + ((size_t)((1 * Bz + b) * Hz + h) * Tz) * DKz;
    const float* Vg = g_qkv + ((size_t)((2 * Bz + b) * Hz + h) * Tz) * DKz;

    const int row0g = q0 + w * 16 + g;
    const int row1g = row0g + 8;

    const int r_ld  = tid >> 4;          // 0..15 (+16 per chunk)
    const int c4_ld = (tid & 15) << 2;   // 0..60

    float4 pk[4], pv[4];
    auto issueKV = [&](int kt) {
#pragma unroll
        for (int it = 0; it < 4; it++) {
            const int r = r_ld + it * 16;
            pk[it] = *(const float4*)(Kg + (size_t)(kt * 64 + r) * DKz + c4_ld);
            pv[it] = *(const float4*)(Vg + (size_t)(kt * 64 + r) * DKz + c4_ld);
        }
    };
    auto storeKV = [&](int buf) {
        uint32_t* sKb = sK + buf * SK_WORDS;
        uint32_t* sVb = sV + buf * SV_WORDS;
#pragma unroll
        for (int it = 0; it < 4; it++) {
            const int r = r_ld + it * 16;
            *(uint4*)&sKb[r * SK_STRIDE + c4_ld] =
                make_uint4(f2tf32(pk[it].x), f2tf32(pk[it].y),
                           f2tf32(pk[it].z), f2tf32(pk[it].w));
            *(uint4*)&sVb[r * SV_STRIDE + c4_ld] =
                make_uint4(f2tf32(pv[it].x), f2tf32(pv[it].y),
                           f2tf32(pv[it].z), f2tf32(pv[it].w));
        }
    };

    // Q fragments (registers)
    uint4 qf[8];
    {
        const float* q0p = Qg + (size_t)row0g * DKz;
        const float* q1p = Qg + (size_t)row1g * DKz;
#pragma unroll
        for (int s = 0; s < 8; s++) {
            qf[s].x = f2tf32(q0p[s * 8 + tig]);
            qf[s].y = f2tf32(q1p[s * 8 + tig]);
            qf[s].z = f2tf32(q0p[s * 8 + tig + 4]);
            qf[s].w = f2tf32(q1p[s * 8 + tig + 4]);
        }
    }

    float acc[8][4];
#pragma unroll
    for (int jd = 0; jd < 8; jd++)
#pragma unroll
        for (int r = 0; r < 4; r++) acc[jd][r] = 0.f;
    float m0 = -1e30f, m1 = -1e30f, l0 = 0.f, l1 = 0.f;

    const int  srcA = (lane & 0x1C) | (tig >> 1);
    const int  srcB = srcA + 2;
    const bool sel  = (tig & 1) != 0;

    issueKV(0);
    storeKV(0);
    __syncthreads();

    const int ktmax = 2 * qblk + 1;
    for (int kt = 0; kt <= ktmax; kt++) {
        const int  p      = kt & 1;
        const bool domask = (kt >= 2 * qblk);

        if (kt < ktmax) issueKV(kt + 1);

        const uint32_t* sKb = sK + p * SK_WORDS;
        const uint32_t* sVb = sV + p * SV_WORDS;

        // ---- S = Q K^T ----
        float sc[8][4];
#pragma unroll
        for (int j = 0; j < 8; j++)
#pragma unroll
            for (int r = 0; r < 4; r++) sc[j][r] = 0.f;
#pragma unroll
        for (int s = 0; s < 8; s++) {
#pragma unroll
            for (int j = 0; j < 8; j++) {
                uint2 bk;
                bk.x = sKb[(j * 8 + g) * SK_STRIDE + s * 8 + tig];
                bk.y = sKb[(j * 8 + g) * SK_STRIDE + s * 8 + tig + 4];
                mma_tf32(sc[j], qf[s], bk);
            }
        }

        // ---- scale + alibi + causal, online softmax (log2 domain) ----
        const int key0 = kt * 64;
        float tmax0 = -1e30f, tmax1 = -1e30f;
#pragma unroll
        for (int j = 0; j < 8; j++) {
            const int ke = key0 + j * 8 + 2 * tig;
            float s00 = fmaf(sc[j][0], sc2, sl2 * (float)(ke - row0g));
            float s01 = fmaf(sc[j][1], sc2, sl2 * (float)(ke + 1 - row0g));
            float s10 = fmaf(sc[j][2], sc2, sl2 * (float)(ke - row1g));
            float s11 = fmaf(sc[j][3], sc2, sl2 * (float)(ke + 1 - row1g));
            if (domask) {
                if (ke     > row0g) s00 = -1e30f;
                if (ke + 1 > row0g) s01 = -1e30f;
                if (ke     > row1g) s10 = -1e30f;
                if (ke + 1 > row1g) s11 = -1e30f;
            }
            sc[j][0] = s00; sc[j][1] = s01; sc[j][2] = s10; sc[j][3] = s11;
            tmax0 = fmaxf(tmax0, fmaxf(s00, s01));
            tmax1 = fmaxf(tmax1, fmaxf(s10, s11));
        }
        tmax0 = fmaxf(tmax0, __shfl_xor_sync(0xffffffffu, tmax0, 1));
        tmax0 = fmaxf(tmax0, __shfl_xor_sync(0xffffffffu, tmax0, 2));
        tmax1 = fmaxf(tmax1, __shfl_xor_sync(0xffffffffu, tmax1, 1));
        tmax1 = fmaxf(tmax1, __shfl_xor_sync(0xffffffffu, tmax1, 2));

        const float mn0 = fmaxf(m0, tmax0);
        const float mn1 = fmaxf(m1, tmax1);
        const float corr0 = fexp2(m0 - mn0);
        const float corr1 = fexp2(m1 - mn1);
        m0 = mn0; m1 = mn1;

        uint4 pu[8];
        float rs0 = 0.f, rs1 = 0.f;
#pragma unroll
        for (int j = 0; j < 8; j++) {
            float p00 = fexp2(sc[j][0] - mn0);
            float p01 = fexp2(sc[j][1] - mn0);
            float p10 = fexp2(sc[j][2] - mn1);
            float p11 = fexp2(sc[j][3] - mn1);
            rs0 += p00 + p01;
            rs1 += p10 + p11;
            pu[j] = make_uint4(f2tf32(p00), f2tf32(p01), f2tf32(p10), f2tf32(p11));
        }
        rs0 += __shfl_xor_sync(0xffffffffu, rs0, 1);
        rs0 += __shfl_xor_sync(0xffffffffu, rs0, 2);
        rs1 += __shfl_xor_sync(0xffffffffu, rs1, 1);
        rs1 += __shfl_xor_sync(0xffffffffu, rs1, 2);
        l0 = l0 * corr0 + rs0;
        l1 = l1 * corr1 + rs1;
#pragma unroll
        for (int jd = 0; jd < 8; jd++) {
            acc[jd][0] *= corr0; acc[jd][1] *= corr0;
            acc[jd][2] *= corr1; acc[jd][3] *= corr1;
        }

        // ---- att += P @ V ----
#pragma unroll
        for (int s = 0; s < 8; s++) {
            uint32_t x00 = __shfl_sync(0xffffffffu, pu[s].x, srcA);
            uint32_t x01 = __shfl_sync(0xffffffffu, pu[s].y, srcA);
            uint32_t x10 = __shfl_sync(0xffffffffu, pu[s].z, srcA);
            uint32_t x11 = __shfl_sync(0xffffffffu, pu[s].w, srcA);
            uint32_t y00 = __shfl_sync(0xffffffffu, pu[s].x, srcB);
            uint32_t y01 = __shfl_sync(0xffffffffu, pu[s].y, srcB);
            uint32_t y10 = __shfl_sync(0xffffffffu, pu[s].z, srcB);
            uint32_t y11 = __shfl_sync(0xffffffffu, pu[s].w, srcB);
            uint4 aP;
            aP.x = sel ? x01 : x00;
            aP.y = sel ? x11 : x10;
            aP.z = sel ? y01 : y00;
            aP.w = sel ? y11 : y10;
#pragma unroll
            for (int jd = 0; jd < 8; jd++) {
                uint2 bv;
                bv.x = sVb[(s * 8 + tig)     * SV_STRIDE + jd * 8 + g];
                bv.y = sVb[(s * 8 + tig + 4) * SV_STRIDE + jd * 8 + g];
                mma_tf32(acc[jd], aP, bv);
            }
        }

        if (kt < ktmax) {
            storeKV(p ^ 1);
            __syncthreads();
        }
    }

    // ---- normalize and write ----
    const float inv0 = 1.f / l0;
    const float inv1 = 1.f / l1;
    float* o0 = g_att + (size_t)(b * Tz + row0g) * Cz + h * DKz;
    float* o1 = g_att + (size_t)(b * Tz + row1g) * Cz + h * DKz;
#pragma unroll
    for (int jd = 0; jd < 8; jd++) {
        *(float2*)(o0 + jd * 8 + 2 * tig) =
            make_float2(acc[jd][0] * inv0, acc[jd][1] * inv0);
        *(float2*)(o1 + jd * 8 + 2 * tig) =
            make_float2(acc[jd][2] * inv1, acc[jd][3] * inv1);
    }
}

// ---------------------------------------------------------------------------
// Launch
// ---------------------------------------------------------------------------
extern "C" void kernel_launch(void* const* d_in, const int* in_sizes, int n_in,
                              void* d_out, int out_size) {
    const float* x     = (const float*)d_in[0];
    const float* alibi = (const float*)d_in[1];
    const float* Wqkv  = (const float*)d_in[2];
    const float* Wo    = (const float*)d_in[3];
    float* out = (float*)d_out;
    (void)in_sizes; (void)n_in; (void)out_size;

    cudaFuncSetAttribute(gemm_tf32<true>,
                         cudaFuncAttributeMaxDynamicSharedMemorySize, GEMM_SMEM_BYTES);
    cudaFuncSetAttribute(gemm_tf32<false>,
                         cudaFuncAttributeMaxDynamicSharedMemorySize, GEMM_SMEM_BYTES);
    cudaFuncSetAttribute(attn_tc,
                         cudaFuncAttributeMaxDynamicSharedMemorySize, ATTN_SMEM_BYTES);

    // 1. QKV projection (TF32, 128x256 tiles), scatters to g_qkv
    gemm_tf32<true><<<dim3(N3z / 256, Mz / 128), 256, GEMM_SMEM_BYTES>>>(x, Wqkv, nullptr);

    // 2. Flash attention with ALiBi (TF32 + FFMA exp), R9-best config
    attn_tc<<<dim3(Tz / 128, Hz, Bz), 256, ATTN_SMEM_BYTES>>>(alibi);

    // 3. Output projection (TF32, 128x256 tiles), A = g_att (device symbol)
    gemm_tf32<false><<<dim3(Cz / 256, Mz / 128), 256, GEMM_SMEM_BYTES>>>(nullptr, Wo, out);
}